// round 8
// baseline (speedup 1.0000x reference)
#include <cuda_runtime.h>
#include <math.h>

// Problem constants
#define B_    32
#define C_    256
#define CR_   64
#define HW_   12544       // 112*112
#define HALF_ 6272        // floats per half-channel
#define NCH   (B_*C_)     // 8192 channels
#define KEEP  2304        // tail channels pinned in L2 (~115.6 MB)

// v8 (32B) tiling for GAP: 12544/8 = 1568 = 6*256 + 32
#define NF8   6
#define NT8   32
// float4 tiling for half-channel scale: 1568 = 6*256 + 32
#define SF4   6
#define ST4   32

__device__ float g_gap[NCH];
__device__ float g_gate[NCH];

struct F8 { float4 a, b; };

__device__ __forceinline__ F8 ld_evict_last8(const float* p) {
    unsigned r0,r1,r2,r3,r4,r5,r6,r7;
    asm("ld.global.L2::evict_last.v8.b32 {%0,%1,%2,%3,%4,%5,%6,%7}, [%8];"
        : "=r"(r0),"=r"(r1),"=r"(r2),"=r"(r3),
          "=r"(r4),"=r"(r5),"=r"(r6),"=r"(r7) : "l"(p));
    F8 v;
    v.a.x = __uint_as_float(r0); v.a.y = __uint_as_float(r1);
    v.a.z = __uint_as_float(r2); v.a.w = __uint_as_float(r3);
    v.b.x = __uint_as_float(r4); v.b.y = __uint_as_float(r5);
    v.b.z = __uint_as_float(r6); v.b.w = __uint_as_float(r7);
    return v;
}

__device__ __forceinline__ F8 ld_evict_first8(const float* p) {
    unsigned r0,r1,r2,r3,r4,r5,r6,r7;
    asm("ld.global.L2::evict_first.v8.b32 {%0,%1,%2,%3,%4,%5,%6,%7}, [%8];"
        : "=r"(r0),"=r"(r1),"=r"(r2),"=r"(r3),
          "=r"(r4),"=r"(r5),"=r"(r6),"=r"(r7) : "l"(p));
    F8 v;
    v.a.x = __uint_as_float(r0); v.a.y = __uint_as_float(r1);
    v.a.z = __uint_as_float(r2); v.a.w = __uint_as_float(r3);
    v.b.x = __uint_as_float(r4); v.b.y = __uint_as_float(r5);
    v.b.z = __uint_as_float(r6); v.b.w = __uint_as_float(r7);
    return v;
}

// ---------------------------------------------------------------------------
// Kernel 1: global average pool. One CTA per (b,c) channel. 32B loads.
// Early channels stream (evict_first); last KEEP channels pinned (evict_last).
// ---------------------------------------------------------------------------
__global__ __launch_bounds__(256) void gap_kernel(const float* __restrict__ x) {
    const int bc = blockIdx.x;
    const int t  = threadIdx.x;
    const float* __restrict__ base = x + (size_t)bc * HW_;
    const bool keep = (bc >= NCH - KEEP);

    F8 v[NF8];
    F8 vt;
    if (keep) {
        #pragma unroll
        for (int k = 0; k < NF8; ++k)
            v[k] = ld_evict_last8(base + (t + k * 256) * 8);
        if (t < NT8) vt = ld_evict_last8(base + (t + NF8 * 256) * 8);
    } else {
        #pragma unroll
        for (int k = 0; k < NF8; ++k)
            v[k] = ld_evict_first8(base + (t + k * 256) * 8);
        if (t < NT8) vt = ld_evict_first8(base + (t + NF8 * 256) * 8);
    }

    float sum = 0.0f;
    #pragma unroll
    for (int k = 0; k < NF8; ++k)
        sum += ((v[k].a.x + v[k].a.y) + (v[k].a.z + v[k].a.w))
             + ((v[k].b.x + v[k].b.y) + (v[k].b.z + v[k].b.w));
    if (t < NT8)
        sum += ((vt.a.x + vt.a.y) + (vt.a.z + vt.a.w))
             + ((vt.b.x + vt.b.y) + (vt.b.z + vt.b.w));

    #pragma unroll
    for (int o = 16; o > 0; o >>= 1)
        sum += __shfl_xor_sync(0xFFFFFFFFu, sum, o);

    __shared__ float s[8];
    if ((t & 31) == 0) s[t >> 5] = sum;
    __syncthreads();
    if (t < 8) {
        sum = s[t];
        #pragma unroll
        for (int o = 4; o > 0; o >>= 1)
            sum += __shfl_xor_sync(0xFFu, sum, o);
        if (t == 0)
            g_gap[bc] = sum * (1.0f / (float)HW_);
    }
}

// ---------------------------------------------------------------------------
// Kernel 2: tiny 2-layer MLP + sigmoid gate. One CTA per batch sample.
// ---------------------------------------------------------------------------
__global__ __launch_bounds__(256) void se_fc_kernel(
    const float* __restrict__ w1, const float* __restrict__ b1,
    const float* __restrict__ w2, const float* __restrict__ b2) {
    const int b = blockIdx.x;
    __shared__ float gap_s[C_];
    __shared__ float h_s[CR_];

    gap_s[threadIdx.x] = g_gap[b * C_ + threadIdx.x];
    __syncthreads();

    if (threadIdx.x < CR_) {
        float acc = b1[threadIdx.x];
        const float* __restrict__ w = w1 + threadIdx.x * C_;
        #pragma unroll 8
        for (int c = 0; c < C_; ++c) acc = fmaf(gap_s[c], w[c], acc);
        h_s[threadIdx.x] = fmaxf(acc, 0.0f);
    }
    __syncthreads();

    float acc = b2[threadIdx.x];
    const float* __restrict__ w = w2 + threadIdx.x * CR_;
    #pragma unroll 8
    for (int o = 0; o < CR_; ++o) acc = fmaf(h_s[o], w[o], acc);
    g_gate[b * C_ + threadIdx.x] = 1.0f / (1.0f + __expf(-acc));
}

// ---------------------------------------------------------------------------
// Kernel 3: out = x * gate. One CTA per HALF-channel (16384 CTAs) for high
// occupancy; reverse order so pinned tail channels are consumed first.
// __ldlu last-use reads; __stcs streaming stores.
// ---------------------------------------------------------------------------
__global__ __launch_bounds__(256) void scale_kernel(
    const float* __restrict__ x, float* __restrict__ out) {
    const int e  = (NCH * 2 - 1) - blockIdx.x;   // reverse unit order
    const int bc = e >> 1;
    const int t  = threadIdx.x;
    const float g = g_gate[bc];
    const size_t off = (size_t)bc * HW_ + (size_t)(e & 1) * HALF_;
    const float4* __restrict__ xp = reinterpret_cast<const float4*>(x + off);
    float4* __restrict__ op = reinterpret_cast<float4*>(out + off);

    float4 v[SF4];
    #pragma unroll
    for (int k = 0; k < SF4; ++k)
        v[k] = __ldlu(xp + t + k * 256);
    float4 vt;
    if (t < ST4) vt = __ldlu(xp + t + SF4 * 256);

    #pragma unroll
    for (int k = 0; k < SF4; ++k) {
        v[k].x *= g; v[k].y *= g; v[k].z *= g; v[k].w *= g;
        __stcs(op + t + k * 256, v[k]);
    }
    if (t < ST4) {
        vt.x *= g; vt.y *= g; vt.z *= g; vt.w *= g;
        __stcs(op + t + SF4 * 256, vt);
    }
}

// ---------------------------------------------------------------------------
extern "C" void kernel_launch(void* const* d_in, const int* in_sizes, int n_in,
                              void* d_out, int out_size) {
    const float* x  = (const float*)d_in[0];
    const float* w1 = (const float*)d_in[1];
    const float* b1 = (const float*)d_in[2];
    const float* w2 = (const float*)d_in[3];
    const float* b2 = (const float*)d_in[4];
    float* out = (float*)d_out;

    gap_kernel<<<NCH, 256>>>(x);
    se_fc_kernel<<<B_, 256>>>(w1, b1, w2, b2);
    scale_kernel<<<NCH * 2, 256>>>(x, out);
}